// round 11
// baseline (speedup 1.0000x reference)
#include <cuda_runtime.h>

#define NB   2
#define LQ   1024
#define LIN  4096
#define CC   256
#define MH   8
#define NP   4
#define SPTS (NB*LQ*MH*NP)   /* 65536 sampling points */

#define GR   32
#define G3   (GR*GR*GR)      /* 32768 cells per batch */

// ---------------- scratch (device globals; no allocation allowed) ----------
__device__ float  g_value[NB*LIN*CC];  // (B, Lin, M, D) = 8 MiB
__device__ float  g_loc[SPTS*3];
__device__ float  g_attw[SPTS];
__device__ int    g_idx[SPTS];
__device__ float  g_mid[NB*LQ*CC];
__device__ float  g_glo[NB][3];
__device__ float  g_gh[NB][3];
__device__ float  g_ghinv[NB][3];
__device__ int    g_cellStart[NB*(G3+1)];
__device__ float4 g_cpts[NB*LIN];      // (x,y,z, idx-bits), cell-sorted

// ---------------- packed helpers --------------------------------------------
typedef unsigned long long u64;
__device__ __forceinline__ u64 pk2(float a, float b) {
    u64 r; asm("mov.b64 %0,{%1,%2};" : "=l"(r) : "f"(a), "f"(b)); return r;
}
__device__ __forceinline__ u64 pkdu(unsigned lo, unsigned hi) {
    u64 r; asm("mov.b64 %0,{%1,%2};" : "=l"(r) : "r"(lo), "r"(hi)); return r;
}
__device__ __forceinline__ u64 ffma2(u64 a, u64 b, u64 c) {
    u64 d; asm("fma.rn.f32x2 %0,%1,%2,%3;" : "=l"(d) : "l"(a), "l"(b), "l"(c)); return d;
}
__device__ __forceinline__ float2 up2(u64 v) {
    float2 f; asm("mov.b64 {%0,%1},%2;" : "=f"(f.x), "=f"(f.y) : "l"(v)); return f;
}

// ---------------- tiled SGEMM-NT 64x64, K=256, BK=16, 256 thr, 4x4 ----------
template<int EPI>
__global__ __launch_bounds__(256)
void sgemm_nt(const float* __restrict__ A,
              const float* __restrict__ W1, const float* __restrict__ W2, int wsplit,
              const float* __restrict__ b1, const float* __restrict__ b2,
              float* __restrict__ Out, int N,
              const float* __restrict__ qpts)
{
    __shared__ float As[16][68];
    __shared__ float Bs[16][68];
    const int tid = threadIdx.x;
    const int tx = tid & 15, ty = tid >> 4;
    const int rowBase = blockIdx.y * 64;
    const int colBase = blockIdx.x * 64;
    const int lr = tid >> 2;
    const int lc = (tid & 3) * 4;

    const float* Aptr = A + (rowBase + lr) * 256 + lc;
    const int wrow = colBase + lr;
    const float* Wptr = (wrow < wsplit) ? (W1 + wrow * 256 + lc)
                                        : (W2 + (wrow - wsplit) * 256 + lc);
    float4 ra = *(const float4*)Aptr;
    float4 rw = *(const float4*)Wptr;

    u64 acc[4][2];
    #pragma unroll
    for (int i = 0; i < 4; i++) { acc[i][0] = 0ull; acc[i][1] = 0ull; }

    for (int kt = 0; kt < 256; kt += 16) {
        As[lc+0][lr] = ra.x; As[lc+1][lr] = ra.y; As[lc+2][lr] = ra.z; As[lc+3][lr] = ra.w;
        Bs[lc+0][lr] = rw.x; Bs[lc+1][lr] = rw.y; Bs[lc+2][lr] = rw.z; Bs[lc+3][lr] = rw.w;
        __syncthreads();
        if (kt < 240) {
            ra = *(const float4*)(Aptr + kt + 16);
            rw = *(const float4*)(Wptr + kt + 16);
        }
        #pragma unroll
        for (int k = 0; k < 16; k++) {
            float4 av = *(const float4*)&As[k][ty * 4];
            float4 bv = *(const float4*)&Bs[k][tx * 4];
            u64 b01 = pk2(bv.x, bv.y), b23 = pk2(bv.z, bv.w);
            u64 a0 = pk2(av.x, av.x), a1 = pk2(av.y, av.y);
            u64 a2 = pk2(av.z, av.z), a3 = pk2(av.w, av.w);
            acc[0][0] = ffma2(a0, b01, acc[0][0]); acc[0][1] = ffma2(a0, b23, acc[0][1]);
            acc[1][0] = ffma2(a1, b01, acc[1][0]); acc[1][1] = ffma2(a1, b23, acc[1][1]);
            acc[2][0] = ffma2(a2, b01, acc[2][0]); acc[2][1] = ffma2(a2, b23, acc[2][1]);
            acc[3][0] = ffma2(a3, b01, acc[3][0]); acc[3][1] = ffma2(a3, b23, acc[3][1]);
        }
        __syncthreads();
    }

    const int c0 = colBase + tx * 4;
    float bias[4];
    #pragma unroll
    for (int j = 0; j < 4; j++) {
        int c = c0 + j;
        bias[j] = (c < wsplit) ? b1[c] : b2[c - wsplit];
    }

    #pragma unroll
    for (int i = 0; i < 4; i++) {
        const int r = rowBase + ty * 4 + i;
        float2 v01 = up2(acc[i][0]);
        float2 v23 = up2(acc[i][1]);
        float v[4] = { v01.x + bias[0], v01.y + bias[1],
                       v23.x + bias[2], v23.y + bias[3] };
        if (EPI == 0) {
            *(float4*)&Out[r * N + c0] = make_float4(v[0], v[1], v[2], v[3]);
        } else {
            if (c0 < 96) {
                #pragma unroll
                for (int j = 0; j < 4; j++) {
                    int c = c0 + j;
                    g_loc[r * 96 + c] = v[j] + qpts[r * 3 + (c % 3)];
                }
            } else {
                float m0 = fmaxf(fmaxf(v[0], v[1]), fmaxf(v[2], v[3]));
                float e0 = __expf(v[0] - m0), e1 = __expf(v[1] - m0);
                float e2 = __expf(v[2] - m0), e3 = __expf(v[3] - m0);
                float inv = 1.0f / (e0 + e1 + e2 + e3);
                int base = r * 32 + (c0 - 96);
                g_attw[base + 0] = e0 * inv;
                g_attw[base + 1] = e1 * inv;
                g_attw[base + 2] = e2 * inv;
                g_attw[base + 3] = e3 * inv;
            }
        }
    }
}

// ---------------- tiled SGEMM-NT 128x128, K=256, BK=16, 256 thr, 8x8 --------
__global__ __launch_bounds__(256)
void sgemm128(const float* __restrict__ A, const float* __restrict__ W,
              const float* __restrict__ bias, float* __restrict__ Out, int N)
{
    __shared__ float As[16][128];
    __shared__ float Bs[16][128];
    const int tid = threadIdx.x;
    const int tx = tid & 15;
    const int ty = tid >> 4;
    const int rowBase = blockIdx.y * 128;
    const int colBase = blockIdx.x * 128;

    const int lr = tid >> 1;
    const int lk = (tid & 1) * 8;
    const float* Aptr = A + (rowBase + lr) * 256 + lk;
    const float* Wptr = W + (colBase + lr) * 256 + lk;
    float4 ra0 = *(const float4*)Aptr;
    float4 ra1 = *(const float4*)(Aptr + 4);
    float4 rw0 = *(const float4*)Wptr;
    float4 rw1 = *(const float4*)(Wptr + 4);

    u64 acc[8][4];
    #pragma unroll
    for (int i = 0; i < 8; i++)
        #pragma unroll
        for (int j = 0; j < 4; j++) acc[i][j] = 0ull;

    for (int kt = 0; kt < 256; kt += 16) {
        As[lk+0][lr] = ra0.x; As[lk+1][lr] = ra0.y; As[lk+2][lr] = ra0.z; As[lk+3][lr] = ra0.w;
        As[lk+4][lr] = ra1.x; As[lk+5][lr] = ra1.y; As[lk+6][lr] = ra1.z; As[lk+7][lr] = ra1.w;
        Bs[lk+0][lr] = rw0.x; Bs[lk+1][lr] = rw0.y; Bs[lk+2][lr] = rw0.z; Bs[lk+3][lr] = rw0.w;
        Bs[lk+4][lr] = rw1.x; Bs[lk+5][lr] = rw1.y; Bs[lk+6][lr] = rw1.z; Bs[lk+7][lr] = rw1.w;
        __syncthreads();
        if (kt < 240) {
            ra0 = *(const float4*)(Aptr + kt + 16);
            ra1 = *(const float4*)(Aptr + kt + 20);
            rw0 = *(const float4*)(Wptr + kt + 16);
            rw1 = *(const float4*)(Wptr + kt + 20);
        }
        #pragma unroll
        for (int k = 0; k < 16; k++) {
            float4 a0 = *(const float4*)&As[k][ty * 8];
            float4 a1 = *(const float4*)&As[k][ty * 8 + 4];
            float4 b0 = *(const float4*)&Bs[k][tx * 8];
            float4 b1 = *(const float4*)&Bs[k][tx * 8 + 4];
            u64 bp[4] = { pk2(b0.x, b0.y), pk2(b0.z, b0.w),
                          pk2(b1.x, b1.y), pk2(b1.z, b1.w) };
            float av[8] = { a0.x, a0.y, a0.z, a0.w, a1.x, a1.y, a1.z, a1.w };
            #pragma unroll
            for (int i = 0; i < 8; i++) {
                u64 ap = pk2(av[i], av[i]);
                #pragma unroll
                for (int j = 0; j < 4; j++)
                    acc[i][j] = ffma2(ap, bp[j], acc[i][j]);
            }
        }
        __syncthreads();
    }

    const int c0 = colBase + tx * 8;
    float4 bia0 = *(const float4*)&bias[c0];
    float4 bia1 = *(const float4*)&bias[c0 + 4];
    #pragma unroll
    for (int i = 0; i < 8; i++) {
        const int r = rowBase + ty * 8 + i;
        float2 v0 = up2(acc[i][0]), v1 = up2(acc[i][1]);
        float2 v2 = up2(acc[i][2]), v3 = up2(acc[i][3]);
        *(float4*)&Out[r * N + c0] =
            make_float4(v0.x + bia0.x, v0.y + bia0.y, v1.x + bia0.z, v1.y + bia0.w);
        *(float4*)&Out[r * N + c0 + 4] =
            make_float4(v2.x + bia1.x, v2.y + bia1.y, v3.x + bia1.z, v3.y + bia1.w);
    }
}

// ---------------- fused grid build: one block per batch ---------------------
#define CPAD(c) ((c) + ((c) >> 5))
#define CNT_WORDS (G3 + (G3 >> 5))

extern __shared__ int s_cnt[];

__device__ __forceinline__ int cell_of(float v, float lo, float hinv) {
    int c = (int)floorf((v - lo) * hinv);
    return min(GR - 1, max(0, c));
}

__global__ __launch_bounds__(512)
void grid_build(const float* __restrict__ ipts)
{
    const int b = blockIdx.x, t = threadIdx.x;
    const int w = t >> 5, l = t & 31;

    float px[8], py[8], pz[8];
    float mnx = 1e30f, mny = 1e30f, mnz = 1e30f;
    float mxx = -1e30f, mxy = -1e30f, mxz = -1e30f;
    #pragma unroll
    for (int j = 0; j < 8; j++) {
        const float* p = ipts + (b*LIN + t + j*512) * 3;
        px[j] = p[0]; py[j] = p[1]; pz[j] = p[2];
        mnx = fminf(mnx, px[j]); mxx = fmaxf(mxx, px[j]);
        mny = fminf(mny, py[j]); mxy = fmaxf(mxy, py[j]);
        mnz = fminf(mnz, pz[j]); mxz = fmaxf(mxz, pz[j]);
    }
    #pragma unroll
    for (int o = 16; o; o >>= 1) {
        mnx = fminf(mnx, __shfl_xor_sync(~0u, mnx, o)); mxx = fmaxf(mxx, __shfl_xor_sync(~0u, mxx, o));
        mny = fminf(mny, __shfl_xor_sync(~0u, mny, o)); mxy = fmaxf(mxy, __shfl_xor_sync(~0u, mxy, o));
        mnz = fminf(mnz, __shfl_xor_sync(~0u, mnz, o)); mxz = fmaxf(mxz, __shfl_xor_sync(~0u, mxz, o));
    }
    __shared__ float red[6][16];
    __shared__ float box[9];
    if (l == 0) {
        red[0][w] = mnx; red[1][w] = mny; red[2][w] = mnz;
        red[3][w] = mxx; red[4][w] = mxy; red[5][w] = mxz;
    }
    __syncthreads();
    if (t == 0) {
        float mn[3], mx[3];
        #pragma unroll
        for (int a = 0; a < 3; a++) { mn[a] = red[a][0]; mx[a] = red[3+a][0]; }
        for (int i = 1; i < 16; i++)
            #pragma unroll
            for (int a = 0; a < 3; a++) {
                mn[a] = fminf(mn[a], red[a][i]);
                mx[a] = fmaxf(mx[a], red[3+a][i]);
            }
        #pragma unroll
        for (int a = 0; a < 3; a++) {
            float lo = mn[a] - 1e-5f;
            float h  = (mx[a] - lo + 1e-5f) / GR;
            box[a] = lo; box[3+a] = h; box[6+a] = 1.0f / h;
            g_glo[b][a] = lo; g_gh[b][a] = h; g_ghinv[b][a] = 1.0f / h;
        }
    }
    __syncthreads();

    for (int i = t; i < CNT_WORDS; i += 512) s_cnt[i] = 0;
    __syncthreads();

    int cell[8];
    #pragma unroll
    for (int j = 0; j < 8; j++) {
        int cx = cell_of(px[j], box[0], box[6]);
        int cy = cell_of(py[j], box[1], box[7]);
        int cz = cell_of(pz[j], box[2], box[8]);
        cell[j] = (cz * GR + cy) * GR + cx;
        atomicAdd(&s_cnt[CPAD(cell[j])], 1);
    }
    __syncthreads();

    const int base = t * 64;
    int sum = 0;
    for (int i = 0; i < 64; i++) sum += s_cnt[CPAD(base + i)];
    int inc = sum;
    #pragma unroll
    for (int o = 1; o < 32; o <<= 1) {
        int v = __shfl_up_sync(~0u, inc, o);
        if (l >= o) inc += v;
    }
    __shared__ int wtot[16];
    if (l == 31) wtot[w] = inc;
    __syncthreads();
    if (t == 0) {
        int run = 0;
        for (int i = 0; i < 16; i++) { int v = wtot[i]; wtot[i] = run; run += v; }
    }
    __syncthreads();
    int run = inc - sum + wtot[w];
    const int cb = b * (G3 + 1);
    for (int i = 0; i < 64; i++) {
        int c = s_cnt[CPAD(base + i)];
        g_cellStart[cb + base + i] = run;
        s_cnt[CPAD(base + i)] = run;
        run += c;
    }
    if (t == 511) g_cellStart[cb + G3] = run;
    __syncthreads();

    #pragma unroll
    for (int j = 0; j < 8; j++) {
        int i = t + j * 512;
        int pos = atomicAdd(&s_cnt[CPAD(cell[j])], 1);
        g_cpts[b*LIN + pos] = make_float4(px[j], py[j], pz[j], __int_as_float(i));
    }
}

// ---------------- warp-cooperative grid 1-NN --------------------------------
// One warp per query (b,q); lane = one of its 32 sampling points (m,p).
// Warp walks expanding Chebyshev shells around the QUERY's cell (uniform
// control flow); candidates stream through smem (coalesced stage ->
// broadcast reads); every lane evaluates every candidate for its own point.
// Winner tracked as u64 key (d_bits<<32)|idx -> exact argmin w/ low-idx tie.
__global__ __launch_bounds__(256)
void knn_query(const float* __restrict__ qpts)
{
    __shared__ float4 stage[8][32];
    const int w = threadIdx.x >> 5, lane = threadIdx.x & 31;
    const int bq = blockIdx.x * 8 + w;      // 0..2047
    const int b  = bq >> 10;
    const int s  = bq * 32 + lane;

    const float sx = g_loc[3*s+0], sy = g_loc[3*s+1], sz = g_loc[3*s+2];
    const float lox = g_glo[b][0], loy = g_glo[b][1], loz = g_glo[b][2];
    const float hx = g_gh[b][0],  hy = g_gh[b][1],  hz = g_gh[b][2];

    const float qx = qpts[bq*3+0], qy = qpts[bq*3+1], qz = qpts[bq*3+2];
    const int cx = cell_of(qx, lox, g_ghinv[b][0]);
    const int cy = cell_of(qy, loy, g_ghinv[b][1]);
    const int cz = cell_of(qz, loz, g_ghinv[b][2]);

    const int cb = b * (G3 + 1);
    const float4* __restrict__ pts = g_cpts + b * LIN;

    u64 bkey = ~0ull;

    auto scanRun = [&](int c0, int c1) {     // inclusive contiguous cell range
        int st = __ldg(&g_cellStart[cb + c0]);
        int en = __ldg(&g_cellStart[cb + c1 + 1]);
        for (int base = st; base < en; base += 32) {
            int n = en - base; if (n > 32) n = 32;
            if (lane < n) stage[w][lane] = __ldg(&pts[base + lane]);
            __syncwarp();
            for (int j = 0; j < n; j++) {
                float4 p = stage[w][j];
                float dx = p.x - sx, dy = p.y - sy, dz = p.z - sz;
                float d = fmaf(dx, dx, fmaf(dy, dy, dz * dz));   // >= 0
                u64 key = pkdu(__float_as_uint(p.w), __float_as_uint(d));
                if (key < bkey) bkey = key;
            }
            __syncwarp();
        }
    };

    for (int r = 0; r <= GR; r++) {          // warp-uniform shells
        const int x0 = max(cx - r, 0), x1 = min(cx + r, GR - 1);
        for (int idz = -r; idz <= r; idz++) {
            int zz = cz + idz;
            if (zz < 0 || zz >= GR) continue;
            bool fz = (idz == -r) || (idz == r);
            for (int idy = -r; idy <= r; idy++) {
                int yy = cy + idy;
                if (yy < 0 || yy >= GR) continue;
                int rowb = (zz * GR + yy) * GR;
                if (fz || idy == -r || idy == r) {
                    scanRun(rowb + x0, rowb + x1);
                } else {
                    if (cx - r >= 0) scanRun(rowb + cx - r, rowb + cx - r);
                    if (cx + r < GR) scanRun(rowb + cx + r, rowb + cx + r);
                }
            }
        }
        // per-lane stop bound: dist from lane's point to nearest unscanned face
        float bestd = __uint_as_float((unsigned)(bkey >> 32));
        float dmin = 1e30f;
        if (cx - r > 0)      dmin = fminf(dmin, sx - (lox + (cx - r) * hx));
        if (cx + r < GR - 1) dmin = fminf(dmin, (lox + (cx + r + 1) * hx) - sx);
        if (cy - r > 0)      dmin = fminf(dmin, sy - (loy + (cy - r) * hy));
        if (cy + r < GR - 1) dmin = fminf(dmin, (loy + (cy + r + 1) * hy) - sy);
        if (cz - r > 0)      dmin = fminf(dmin, sz - (loz + (cz - r) * hz));
        if (cz + r < GR - 1) dmin = fminf(dmin, (loz + (cz + r + 1) * hz) - sz);
        bool done;
        if (dmin > 1e29f) done = true;       // whole grid scanned
        else { dmin = fmaxf(dmin, 0.0f); done = (bestd < dmin * dmin); }
        if (__all_sync(0xffffffffu, done)) break;
    }
    g_idx[s] = (int)(unsigned)(bkey & 0xffffffffu);
}

// ---------------- gather + weighted sum over P -------------------------------
__global__ __launch_bounds__(256)
void gather_kernel()
{
    const int g    = (blockIdx.x * 256 + threadIdx.x) >> 5;  // bq*8 + m
    const int lane = threadIdx.x & 31;
    const int m  = g & 7;
    const int bq = g >> 3;
    const int b  = bq >> 10;
    const int base = bq * 32 + m * 4;
    const float4 aw = *(const float4*)&g_attw[base];
    const int4   li = *(const int4*)&g_idx[base];
    float acc = aw.x * g_value[(b * LIN + li.x) * CC + m * 32 + lane];
    acc += aw.y * g_value[(b * LIN + li.y) * CC + m * 32 + lane];
    acc += aw.z * g_value[(b * LIN + li.z) * CC + m * 32 + lane];
    acc += aw.w * g_value[(b * LIN + li.w) * CC + m * 32 + lane];
    g_mid[bq * CC + m * 32 + lane] = acc;
}

// ---------------------------------------------------------------------------
extern "C" void kernel_launch(void* const* d_in, const int* in_sizes, int n_in,
                              void* d_out, int out_size) {
    const float* query = (const float*)d_in[0];
    const float* qpts  = (const float*)d_in[1];
    const float* inp   = (const float*)d_in[2];
    const float* ipts  = (const float*)d_in[3];
    const float* Wv    = (const float*)d_in[4];
    const float* bv    = (const float*)d_in[5];
    const float* Ws    = (const float*)d_in[6];
    const float* bs    = (const float*)d_in[7];
    const float* Wa    = (const float*)d_in[8];
    const float* ba    = (const float*)d_in[9];
    const float* Wo    = (const float*)d_in[10];
    const float* bo    = (const float*)d_in[11];
    float* out = (float*)d_out;

    float *p_value, *p_mid;
    cudaGetSymbolAddress((void**)&p_value, g_value);
    cudaGetSymbolAddress((void**)&p_mid,   g_mid);

    const int BIG = 1 << 30;
    const int smemBytes = CNT_WORDS * sizeof(int);

    static cudaStream_t s1 = nullptr;
    static cudaEvent_t evFork = nullptr, evJoin = nullptr;
    if (!s1) {
        cudaStreamCreateWithFlags(&s1, cudaStreamNonBlocking);
        cudaEventCreateWithFlags(&evFork, cudaEventDisableTiming);
        cudaEventCreateWithFlags(&evJoin, cudaEventDisableTiming);
        cudaFuncSetAttribute(grid_build,
                             cudaFuncAttributeMaxDynamicSharedMemorySize, smemBytes);
    }

    // fork: value GEMM on side stream (independent of everything else)
    cudaEventRecord(evFork, 0);
    cudaStreamWaitEvent(s1, evFork, 0);
    sgemm128<<<dim3(2, 64), 256, 0, s1>>>(inp, Wv, bv, p_value, 256);
    cudaEventRecord(evJoin, s1);

    // main stream: grid build -> proj (-> g_loc/g_attw) -> warp-coop 1-NN
    grid_build<<<NB, 512, smemBytes>>>(ipts);
    sgemm_nt<1><<<dim3(2, 32), 256>>>(query, Ws, Wa, 96, bs, ba,
                                      nullptr, 128, qpts);
    knn_query<<<256, 256>>>(qpts);

    // join: gather needs knn results and g_value
    cudaStreamWaitEvent(0, evJoin, 0);
    gather_kernel<<<2048, 256>>>();
    sgemm_nt<0><<<dim3(4, 32), 256>>>(p_mid, Wo, Wo, BIG, bo, bo,
                                      out, 256, nullptr);
}

// round 13
// speedup vs baseline: 2.9111x; 2.9111x over previous
#include <cuda_runtime.h>

#define NB   2
#define LQ   1024
#define LIN  4096
#define CC   256
#define MH   8
#define NP   4
#define SPTS (NB*LQ*MH*NP)   /* 65536 sampling points */
#define NE   8               /* candidate eighths */

// ---------------- scratch (device globals; no allocation allowed) ----------
__device__ float g_value[NB*LIN*CC];   // (B, Lin, M, D) = 8 MiB
__device__ float g_loc[SPTS*3];        // sampling locations
__device__ float g_attw[SPTS];         // softmaxed attention weights
__device__ float g_bd2[SPTS*NE];       // best distance  [sp][eighth]
__device__ int   g_bi2[SPTS*NE];       // best index     [sp][eighth]
__device__ float g_mid[NB*LQ*CC];      // pre-output-projection features

// ---------------- packed f32x2 helpers --------------------------------------
typedef unsigned long long u64;
__device__ __forceinline__ u64 pk2(float a, float b) {
    u64 r; asm("mov.b64 %0,{%1,%2};" : "=l"(r) : "f"(a), "f"(b)); return r;
}
__device__ __forceinline__ u64 ffma2(u64 a, u64 b, u64 c) {
    u64 d; asm("fma.rn.f32x2 %0,%1,%2,%3;" : "=l"(d) : "l"(a), "l"(b), "l"(c)); return d;
}
__device__ __forceinline__ float2 up2(u64 v) {
    float2 f; asm("mov.b64 {%0,%1},%2;" : "=f"(f.x), "=f"(f.y) : "l"(v)); return f;
}

// ---------------- tiled SGEMM-NT 64x64, K=256, BK=16, 256 thr, 4x4 ----------
// (small GEMMs: proj 2048x128 with epilogue, out 2048x256)
template<int EPI>
__global__ __launch_bounds__(256)
void sgemm_nt(const float* __restrict__ A,
              const float* __restrict__ W1, const float* __restrict__ W2, int wsplit,
              const float* __restrict__ b1, const float* __restrict__ b2,
              float* __restrict__ Out, int N,
              const float* __restrict__ qpts)
{
    __shared__ float As[16][68];
    __shared__ float Bs[16][68];
    const int tid = threadIdx.x;
    const int tx = tid & 15, ty = tid >> 4;
    const int rowBase = blockIdx.y * 64;
    const int colBase = blockIdx.x * 64;
    const int lr = tid >> 2;
    const int lc = (tid & 3) * 4;

    const float* Aptr = A + (rowBase + lr) * 256 + lc;
    const int wrow = colBase + lr;
    const float* Wptr = (wrow < wsplit) ? (W1 + wrow * 256 + lc)
                                        : (W2 + (wrow - wsplit) * 256 + lc);
    float4 ra = *(const float4*)Aptr;
    float4 rw = *(const float4*)Wptr;

    u64 acc[4][2];
    #pragma unroll
    for (int i = 0; i < 4; i++) { acc[i][0] = 0ull; acc[i][1] = 0ull; }

    for (int kt = 0; kt < 256; kt += 16) {
        As[lc+0][lr] = ra.x; As[lc+1][lr] = ra.y; As[lc+2][lr] = ra.z; As[lc+3][lr] = ra.w;
        Bs[lc+0][lr] = rw.x; Bs[lc+1][lr] = rw.y; Bs[lc+2][lr] = rw.z; Bs[lc+3][lr] = rw.w;
        __syncthreads();
        if (kt < 240) {
            ra = *(const float4*)(Aptr + kt + 16);
            rw = *(const float4*)(Wptr + kt + 16);
        }
        #pragma unroll
        for (int k = 0; k < 16; k++) {
            float4 av = *(const float4*)&As[k][ty * 4];
            float4 bv = *(const float4*)&Bs[k][tx * 4];
            u64 b01 = pk2(bv.x, bv.y), b23 = pk2(bv.z, bv.w);
            u64 a0 = pk2(av.x, av.x), a1 = pk2(av.y, av.y);
            u64 a2 = pk2(av.z, av.z), a3 = pk2(av.w, av.w);
            acc[0][0] = ffma2(a0, b01, acc[0][0]); acc[0][1] = ffma2(a0, b23, acc[0][1]);
            acc[1][0] = ffma2(a1, b01, acc[1][0]); acc[1][1] = ffma2(a1, b23, acc[1][1]);
            acc[2][0] = ffma2(a2, b01, acc[2][0]); acc[2][1] = ffma2(a2, b23, acc[2][1]);
            acc[3][0] = ffma2(a3, b01, acc[3][0]); acc[3][1] = ffma2(a3, b23, acc[3][1]);
        }
        __syncthreads();
    }

    const int c0 = colBase + tx * 4;
    float bias[4];
    #pragma unroll
    for (int j = 0; j < 4; j++) {
        int c = c0 + j;
        bias[j] = (c < wsplit) ? b1[c] : b2[c - wsplit];
    }

    #pragma unroll
    for (int i = 0; i < 4; i++) {
        const int r = rowBase + ty * 4 + i;
        float2 v01 = up2(acc[i][0]);
        float2 v23 = up2(acc[i][1]);
        float v[4] = { v01.x + bias[0], v01.y + bias[1],
                       v23.x + bias[2], v23.y + bias[3] };
        if (EPI == 0) {
            *(float4*)&Out[r * N + c0] = make_float4(v[0], v[1], v[2], v[3]);
        } else {
            if (c0 < 96) {
                #pragma unroll
                for (int j = 0; j < 4; j++) {
                    int c = c0 + j;
                    g_loc[r * 96 + c] = v[j] + qpts[r * 3 + (c % 3)];
                }
            } else {
                float m0 = fmaxf(fmaxf(v[0], v[1]), fmaxf(v[2], v[3]));
                float e0 = __expf(v[0] - m0), e1 = __expf(v[1] - m0);
                float e2 = __expf(v[2] - m0), e3 = __expf(v[3] - m0);
                float inv = 1.0f / (e0 + e1 + e2 + e3);
                int base = r * 32 + (c0 - 96);
                g_attw[base + 0] = e0 * inv;
                g_attw[base + 1] = e1 * inv;
                g_attw[base + 2] = e2 * inv;
                g_attw[base + 3] = e3 * inv;
            }
        }
    }
}

// ---------------- tiled SGEMM-NT 128x128, K=256, BK=16, 256 thr, 8x8 --------
__global__ __launch_bounds__(256)
void sgemm128(const float* __restrict__ A, const float* __restrict__ W,
              const float* __restrict__ bias, float* __restrict__ Out, int N)
{
    __shared__ float As[16][128];
    __shared__ float Bs[16][128];
    const int tid = threadIdx.x;
    const int tx = tid & 15;
    const int ty = tid >> 4;
    const int rowBase = blockIdx.y * 128;
    const int colBase = blockIdx.x * 128;

    const int lr = tid >> 1;
    const int lk = (tid & 1) * 8;
    const float* Aptr = A + (rowBase + lr) * 256 + lk;
    const float* Wptr = W + (colBase + lr) * 256 + lk;
    float4 ra0 = *(const float4*)Aptr;
    float4 ra1 = *(const float4*)(Aptr + 4);
    float4 rw0 = *(const float4*)Wptr;
    float4 rw1 = *(const float4*)(Wptr + 4);

    u64 acc[8][4];
    #pragma unroll
    for (int i = 0; i < 8; i++)
        #pragma unroll
        for (int j = 0; j < 4; j++) acc[i][j] = 0ull;

    for (int kt = 0; kt < 256; kt += 16) {
        As[lk+0][lr] = ra0.x; As[lk+1][lr] = ra0.y; As[lk+2][lr] = ra0.z; As[lk+3][lr] = ra0.w;
        As[lk+4][lr] = ra1.x; As[lk+5][lr] = ra1.y; As[lk+6][lr] = ra1.z; As[lk+7][lr] = ra1.w;
        Bs[lk+0][lr] = rw0.x; Bs[lk+1][lr] = rw0.y; Bs[lk+2][lr] = rw0.z; Bs[lk+3][lr] = rw0.w;
        Bs[lk+4][lr] = rw1.x; Bs[lk+5][lr] = rw1.y; Bs[lk+6][lr] = rw1.z; Bs[lk+7][lr] = rw1.w;
        __syncthreads();
        if (kt < 240) {
            ra0 = *(const float4*)(Aptr + kt + 16);
            ra1 = *(const float4*)(Aptr + kt + 20);
            rw0 = *(const float4*)(Wptr + kt + 16);
            rw1 = *(const float4*)(Wptr + kt + 20);
        }
        #pragma unroll
        for (int k = 0; k < 16; k++) {
            float4 a0 = *(const float4*)&As[k][ty * 8];
            float4 a1 = *(const float4*)&As[k][ty * 8 + 4];
            float4 b0 = *(const float4*)&Bs[k][tx * 8];
            float4 b1 = *(const float4*)&Bs[k][tx * 8 + 4];
            u64 bp[4] = { pk2(b0.x, b0.y), pk2(b0.z, b0.w),
                          pk2(b1.x, b1.y), pk2(b1.z, b1.w) };
            float av[8] = { a0.x, a0.y, a0.z, a0.w, a1.x, a1.y, a1.z, a1.w };
            #pragma unroll
            for (int i = 0; i < 8; i++) {
                u64 ap = pk2(av[i], av[i]);
                #pragma unroll
                for (int j = 0; j < 4; j++)
                    acc[i][j] = ffma2(ap, bp[j], acc[i][j]);
            }
        }
        __syncthreads();
    }

    const int c0 = colBase + tx * 8;
    float4 bia0 = *(const float4*)&bias[c0];
    float4 bia1 = *(const float4*)&bias[c0 + 4];
    #pragma unroll
    for (int i = 0; i < 8; i++) {
        const int r = rowBase + ty * 8 + i;
        float2 v0 = up2(acc[i][0]), v1 = up2(acc[i][1]);
        float2 v2 = up2(acc[i][2]), v3 = up2(acc[i][3]);
        *(float4*)&Out[r * N + c0] =
            make_float4(v0.x + bia0.x, v0.y + bia0.y, v1.x + bia0.z, v1.y + bia0.w);
        *(float4*)&Out[r * N + c0 + 4] =
            make_float4(v2.x + bia1.x, v2.y + bia1.y, v3.x + bia1.z, v3.y + bia1.w);
    }
}

// ---------------- brute-force 1-NN: superblock min, 512 blocks --------------
// 512 blocks = 64 s-blocks x 8 candidate-eighths (512 cand each, 8KB smem)
// -> 3.46 blocks/SM: wave-quantization imbalance 1.16x instead of the 2.0x
//    of the old 256-block layout.
// Inner loop keeps running scalar minima on both halves of each packed
// distance (register-pair halves are free to address); one compare+select
// per 64-candidate superblock; exact winning slot recovered by a
// bit-identical rescan. argmin first-min semantics preserved end to end.
__global__ __launch_bounds__(256)
void knn_kernel(const float* __restrict__ ipts)
{
    __shared__ __align__(16) float xs[512];
    __shared__ __align__(16) float ys[512];
    __shared__ __align__(16) float zs[512];
    __shared__ __align__(16) float wsq[512];

    const int tid  = threadIdx.x;
    const int sblk = blockIdx.x >> 3;      // 0..63
    const int e    = blockIdx.x & 7;       // candidate eighth
    const int sbase = sblk * 1024;
    const int b = sbase >> 15;
    const int cbase = b * LIN + e * 512;

    for (int i = tid; i < 512; i += 256) {
        float x = ipts[(cbase + i) * 3 + 0];
        float y = ipts[(cbase + i) * 3 + 1];
        float z = ipts[(cbase + i) * 3 + 2];
        xs[i] = x; ys[i] = y; zs[i] = z;
        wsq[i] = x * x + y * y + z * z;
    }
    __syncthreads();

    int   s[4], bsb[4];
    float best[4];
    u64 ax2[4], ay2[4], az2[4];
    #pragma unroll
    for (int k = 0; k < 4; k++) {
        s[k] = sbase + k * 256 + tid;
        float sx = g_loc[3 * s[k] + 0];
        float sy = g_loc[3 * s[k] + 1];
        float sz = g_loc[3 * s[k] + 2];
        float ax = -2.0f * sx, ay = -2.0f * sy, az = -2.0f * sz;
        ax2[k] = pk2(ax, ax); ay2[k] = pk2(ay, ay); az2[k] = pk2(az, az);
        best[k] = 3.4e38f; bsb[k] = 0;
    }

    const u64* X  = (const u64*)xs;
    const u64* Y  = (const u64*)ys;
    const u64* Z  = (const u64*)zs;
    const u64* Wq = (const u64*)wsq;

    // 8 superblocks of 64 candidates (32 u64 pairs each)
    #pragma unroll 1
    for (int sb = 0; sb < 8; sb++) {
        float mlo[4] = {3.4e38f, 3.4e38f, 3.4e38f, 3.4e38f};
        float mhi[4] = {3.4e38f, 3.4e38f, 3.4e38f, 3.4e38f};
        const int o0 = sb * 32;
        #pragma unroll 8
        for (int j = 0; j < 32; j++) {
            u64 xv = X[o0+j], yv = Y[o0+j], zv = Z[o0+j], wv = Wq[o0+j];
            #pragma unroll
            for (int k = 0; k < 4; k++) {
                u64 d2 = ffma2(xv, ax2[k], wv);
                d2 = ffma2(yv, ay2[k], d2);
                d2 = ffma2(zv, az2[k], d2);
                float2 f = up2(d2);                  // free: register halves
                mlo[k] = fminf(mlo[k], f.x);
                mhi[k] = fminf(mhi[k], f.y);
            }
        }
        #pragma unroll
        for (int k = 0; k < 4; k++) {
            float m = fminf(mlo[k], mhi[k]);
            if (m < best[k]) { best[k] = m; bsb[k] = sb; }  // strict <: earliest sb
        }
    }

    // recovery: rescan winning superblock, first index equal to best wins
    #pragma unroll
    for (int k = 0; k < 4; k++) {
        const int o0 = bsb[k] * 32;
        int idx = 0;
        bool found = false;
        for (int j = 0; j < 32; j++) {
            u64 d2 = ffma2(X[o0+j], ax2[k], Wq[o0+j]);
            d2 = ffma2(Y[o0+j], ay2[k], d2);
            d2 = ffma2(Z[o0+j], az2[k], d2);
            float2 f = up2(d2);
            if (!found && f.x == best[k]) { idx = (o0 + j) * 2;     found = true; }
            if (!found && f.y == best[k]) { idx = (o0 + j) * 2 + 1; found = true; }
        }
        g_bd2[s[k]*NE + e] = best[k];
        g_bi2[s[k]*NE + e] = e * 512 + idx;
    }
}

// ---------------- combine eighths + gather + weighted sum -------------------
__global__ __launch_bounds__(256)
void gather_kernel()
{
    const int g    = (blockIdx.x * 256 + threadIdx.x) >> 5;  // bq*8 + m
    const int lane = threadIdx.x & 31;
    const int m  = g & 7;
    const int bq = g >> 3;
    const int b  = bq >> 10;
    const int base = bq * 32 + m * 4;
    const float4 aw = *(const float4*)&g_attw[base];
    const float w4[4] = { aw.x, aw.y, aw.z, aw.w };
    float acc = 0.0f;
    #pragma unroll
    for (int p = 0; p < 4; p++) {
        const int spE = (base + p) * NE;
        float4 bd0 = *(const float4*)&g_bd2[spE];
        float4 bd1 = *(const float4*)&g_bd2[spE + 4];
        int4   bi0 = *(const int4*)&g_bi2[spE];
        int4   bi1 = *(const int4*)&g_bi2[spE + 4];
        float bdm = bd0.x; int l = bi0.x;            // ascending eighth, strict <
        if (bd0.y < bdm) { bdm = bd0.y; l = bi0.y; } // -> global first-min
        if (bd0.z < bdm) { bdm = bd0.z; l = bi0.z; }
        if (bd0.w < bdm) { bdm = bd0.w; l = bi0.w; }
        if (bd1.x < bdm) { bdm = bd1.x; l = bi1.x; }
        if (bd1.y < bdm) { bdm = bd1.y; l = bi1.y; }
        if (bd1.z < bdm) { bdm = bd1.z; l = bi1.z; }
        if (bd1.w < bdm) { bdm = bd1.w; l = bi1.w; }
        acc += w4[p] * g_value[(b * LIN + l) * CC + m * 32 + lane];
    }
    g_mid[bq * CC + m * 32 + lane] = acc;
}

// ---------------------------------------------------------------------------
extern "C" void kernel_launch(void* const* d_in, const int* in_sizes, int n_in,
                              void* d_out, int out_size) {
    const float* query = (const float*)d_in[0];
    const float* qpts  = (const float*)d_in[1];
    const float* inp   = (const float*)d_in[2];
    const float* ipts  = (const float*)d_in[3];
    const float* Wv    = (const float*)d_in[4];
    const float* bv    = (const float*)d_in[5];
    const float* Ws    = (const float*)d_in[6];
    const float* bs    = (const float*)d_in[7];
    const float* Wa    = (const float*)d_in[8];
    const float* ba    = (const float*)d_in[9];
    const float* Wo    = (const float*)d_in[10];
    const float* bo    = (const float*)d_in[11];
    float* out = (float*)d_out;

    float *p_value, *p_mid;
    cudaGetSymbolAddress((void**)&p_value, g_value);
    cudaGetSymbolAddress((void**)&p_mid,   g_mid);

    const int BIG = 1 << 30;

    static cudaStream_t s1 = nullptr;
    static cudaEvent_t evFork = nullptr, evJoin = nullptr;
    if (!s1) {
        cudaStreamCreateWithFlags(&s1, cudaStreamNonBlocking);
        cudaEventCreateWithFlags(&evFork, cudaEventDisableTiming);
        cudaEventCreateWithFlags(&evJoin, cudaEventDisableTiming);
    }

    // fork: value GEMM on side stream (independent of proj/knn)
    cudaEventRecord(evFork, 0);
    cudaStreamWaitEvent(s1, evFork, 0);
    sgemm128<<<dim3(2, 64), 256, 0, s1>>>(inp, Wv, bv, p_value, 256);
    cudaEventRecord(evJoin, s1);

    // main stream: proj (-> g_loc, g_attw), then KNN (512 balanced blocks)
    sgemm_nt<1><<<dim3(2, 32), 256>>>(query, Ws, Wa, 96, bs, ba,
                                      nullptr, 128, qpts);
    knn_kernel<<<512, 256>>>(ipts);

    // join: gather needs both knn results and g_value
    cudaStreamWaitEvent(0, evJoin, 0);
    gather_kernel<<<2048, 256>>>();
    sgemm_nt<0><<<dim3(4, 32), 256>>>(p_mid, Wo, Wo, BIG, bo, bo,
                                      out, 256, nullptr);
}

// round 14
// speedup vs baseline: 4.1413x; 1.4226x over previous
#include <cuda_runtime.h>

#define NB   2
#define LQ   1024
#define LIN  4096
#define CC   256
#define MH   8
#define NP   4
#define SPTS (NB*LQ*MH*NP)   /* 65536 sampling points */

// ---------------- scratch (device globals; no allocation allowed) ----------
__device__ float g_value[NB*LIN*CC];   // (B, Lin, M, D) = 8 MiB
__device__ float g_loc[SPTS*3];        // sampling locations
__device__ float g_attw[SPTS];         // softmaxed attention weights
__device__ float g_bd2[SPTS*4];        // best distance  [sp][quarter]
__device__ int   g_bi2[SPTS*4];        // best index     [sp][quarter]
__device__ float g_mid[NB*LQ*CC];      // pre-output-projection features

// ---------------- packed f32x2 helpers --------------------------------------
typedef unsigned long long u64;
__device__ __forceinline__ u64 pk2(float a, float b) {
    u64 r; asm("mov.b64 %0,{%1,%2};" : "=l"(r) : "f"(a), "f"(b)); return r;
}
__device__ __forceinline__ u64 ffma2(u64 a, u64 b, u64 c) {
    u64 d; asm("fma.rn.f32x2 %0,%1,%2,%3;" : "=l"(d) : "l"(a), "l"(b), "l"(c)); return d;
}
__device__ __forceinline__ float2 up2(u64 v) {
    float2 f; asm("mov.b64 {%0,%1},%2;" : "=f"(f.x), "=f"(f.y) : "l"(v)); return f;
}

// ---------------- tiled SGEMM-NT 64x64, K=256, BK=16, 256 thr, 4x4 ----------
// (proj GEMM 2048x128 with fused location/softmax epilogue)
template<int EPI>
__global__ __launch_bounds__(256)
void sgemm_nt(const float* __restrict__ A,
              const float* __restrict__ W1, const float* __restrict__ W2, int wsplit,
              const float* __restrict__ b1, const float* __restrict__ b2,
              float* __restrict__ Out, int N,
              const float* __restrict__ qpts)
{
    __shared__ float As[16][68];
    __shared__ float Bs[16][68];
    const int tid = threadIdx.x;
    const int tx = tid & 15, ty = tid >> 4;
    const int rowBase = blockIdx.y * 64;
    const int colBase = blockIdx.x * 64;
    const int lr = tid >> 2;
    const int lc = (tid & 3) * 4;

    const float* Aptr = A + (rowBase + lr) * 256 + lc;
    const int wrow = colBase + lr;
    const float* Wptr = (wrow < wsplit) ? (W1 + wrow * 256 + lc)
                                        : (W2 + (wrow - wsplit) * 256 + lc);
    float4 ra = *(const float4*)Aptr;
    float4 rw = *(const float4*)Wptr;

    u64 acc[4][2];
    #pragma unroll
    for (int i = 0; i < 4; i++) { acc[i][0] = 0ull; acc[i][1] = 0ull; }

    for (int kt = 0; kt < 256; kt += 16) {
        As[lc+0][lr] = ra.x; As[lc+1][lr] = ra.y; As[lc+2][lr] = ra.z; As[lc+3][lr] = ra.w;
        Bs[lc+0][lr] = rw.x; Bs[lc+1][lr] = rw.y; Bs[lc+2][lr] = rw.z; Bs[lc+3][lr] = rw.w;
        __syncthreads();
        if (kt < 240) {
            ra = *(const float4*)(Aptr + kt + 16);
            rw = *(const float4*)(Wptr + kt + 16);
        }
        #pragma unroll
        for (int k = 0; k < 16; k++) {
            float4 av = *(const float4*)&As[k][ty * 4];
            float4 bv = *(const float4*)&Bs[k][tx * 4];
            u64 b01 = pk2(bv.x, bv.y), b23 = pk2(bv.z, bv.w);
            u64 a0 = pk2(av.x, av.x), a1 = pk2(av.y, av.y);
            u64 a2 = pk2(av.z, av.z), a3 = pk2(av.w, av.w);
            acc[0][0] = ffma2(a0, b01, acc[0][0]); acc[0][1] = ffma2(a0, b23, acc[0][1]);
            acc[1][0] = ffma2(a1, b01, acc[1][0]); acc[1][1] = ffma2(a1, b23, acc[1][1]);
            acc[2][0] = ffma2(a2, b01, acc[2][0]); acc[2][1] = ffma2(a2, b23, acc[2][1]);
            acc[3][0] = ffma2(a3, b01, acc[3][0]); acc[3][1] = ffma2(a3, b23, acc[3][1]);
        }
        __syncthreads();
    }

    const int c0 = colBase + tx * 4;
    float bias[4];
    #pragma unroll
    for (int j = 0; j < 4; j++) {
        int c = c0 + j;
        bias[j] = (c < wsplit) ? b1[c] : b2[c - wsplit];
    }

    #pragma unroll
    for (int i = 0; i < 4; i++) {
        const int r = rowBase + ty * 4 + i;
        float2 v01 = up2(acc[i][0]);
        float2 v23 = up2(acc[i][1]);
        float v[4] = { v01.x + bias[0], v01.y + bias[1],
                       v23.x + bias[2], v23.y + bias[3] };
        if (EPI == 0) {
            *(float4*)&Out[r * N + c0] = make_float4(v[0], v[1], v[2], v[3]);
        } else {
            if (c0 < 96) {
                #pragma unroll
                for (int j = 0; j < 4; j++) {
                    int c = c0 + j;
                    g_loc[r * 96 + c] = v[j] + qpts[r * 3 + (c % 3)];
                }
            } else {
                float m0 = fmaxf(fmaxf(v[0], v[1]), fmaxf(v[2], v[3]));
                float e0 = __expf(v[0] - m0), e1 = __expf(v[1] - m0);
                float e2 = __expf(v[2] - m0), e3 = __expf(v[3] - m0);
                float inv = 1.0f / (e0 + e1 + e2 + e3);
                int base = r * 32 + (c0 - 96);
                g_attw[base + 0] = e0 * inv;
                g_attw[base + 1] = e1 * inv;
                g_attw[base + 2] = e2 * inv;
                g_attw[base + 3] = e3 * inv;
            }
        }
    }
}

// ---------------- tiled SGEMM-NT 32x64, K=256, BK=16, 256 thr, 2x4 ----------
// Out-projection: 256 blocks (2 per SM) for latency hiding vs the 64x64
// kernel's single 8-warp block per SM (measured occ 12.7%, 15us).
__global__ __launch_bounds__(256)
void sgemm32x64(const float* __restrict__ A, const float* __restrict__ W,
                const float* __restrict__ bias, float* __restrict__ Out, int N)
{
    __shared__ float As[16][36];
    __shared__ float Bs[16][68];
    const int tid = threadIdx.x;
    const int tx = tid & 15, ty = tid >> 4;
    const int rowBase = blockIdx.y * 32;
    const int colBase = blockIdx.x * 64;

    const int lrA = tid >> 3;            // 0..31
    const int lcA = (tid & 7) * 2;       // 0..14
    const int lrB = tid >> 2;            // 0..63
    const int lcB = (tid & 3) * 4;       // 0,4,8,12

    const float* Aptr = A + (rowBase + lrA) * 256 + lcA;
    const float* Wptr = W + (colBase + lrB) * 256 + lcB;
    float2 ra = *(const float2*)Aptr;
    float4 rw = *(const float4*)Wptr;

    u64 acc[2][2] = {{0ull, 0ull}, {0ull, 0ull}};

    for (int kt = 0; kt < 256; kt += 16) {
        As[lcA+0][lrA] = ra.x; As[lcA+1][lrA] = ra.y;
        Bs[lcB+0][lrB] = rw.x; Bs[lcB+1][lrB] = rw.y;
        Bs[lcB+2][lrB] = rw.z; Bs[lcB+3][lrB] = rw.w;
        __syncthreads();
        if (kt < 240) {
            ra = *(const float2*)(Aptr + kt + 16);
            rw = *(const float4*)(Wptr + kt + 16);
        }
        #pragma unroll
        for (int k = 0; k < 16; k++) {
            float2 av = *(const float2*)&As[k][ty * 2];
            float4 bv = *(const float4*)&Bs[k][tx * 4];
            u64 b01 = pk2(bv.x, bv.y), b23 = pk2(bv.z, bv.w);
            u64 a0 = pk2(av.x, av.x), a1 = pk2(av.y, av.y);
            acc[0][0] = ffma2(a0, b01, acc[0][0]); acc[0][1] = ffma2(a0, b23, acc[0][1]);
            acc[1][0] = ffma2(a1, b01, acc[1][0]); acc[1][1] = ffma2(a1, b23, acc[1][1]);
        }
        __syncthreads();
    }

    const int c0 = colBase + tx * 4;
    float4 bia = *(const float4*)&bias[c0];
    #pragma unroll
    for (int i = 0; i < 2; i++) {
        const int r = rowBase + ty * 2 + i;
        float2 v01 = up2(acc[i][0]);
        float2 v23 = up2(acc[i][1]);
        *(float4*)&Out[r * N + c0] =
            make_float4(v01.x + bia.x, v01.y + bia.y, v23.x + bia.z, v23.y + bia.w);
    }
}

// ---------------- tiled SGEMM-NT 128x128, K=256, BK=16, 256 thr, 8x8 --------
__global__ __launch_bounds__(256)
void sgemm128(const float* __restrict__ A, const float* __restrict__ W,
              const float* __restrict__ bias, float* __restrict__ Out, int N)
{
    __shared__ float As[16][128];
    __shared__ float Bs[16][128];
    const int tid = threadIdx.x;
    const int tx = tid & 15;
    const int ty = tid >> 4;
    const int rowBase = blockIdx.y * 128;
    const int colBase = blockIdx.x * 128;

    const int lr = tid >> 1;
    const int lk = (tid & 1) * 8;
    const float* Aptr = A + (rowBase + lr) * 256 + lk;
    const float* Wptr = W + (colBase + lr) * 256 + lk;
    float4 ra0 = *(const float4*)Aptr;
    float4 ra1 = *(const float4*)(Aptr + 4);
    float4 rw0 = *(const float4*)Wptr;
    float4 rw1 = *(const float4*)(Wptr + 4);

    u64 acc[8][4];
    #pragma unroll
    for (int i = 0; i < 8; i++)
        #pragma unroll
        for (int j = 0; j < 4; j++) acc[i][j] = 0ull;

    for (int kt = 0; kt < 256; kt += 16) {
        As[lk+0][lr] = ra0.x; As[lk+1][lr] = ra0.y; As[lk+2][lr] = ra0.z; As[lk+3][lr] = ra0.w;
        As[lk+4][lr] = ra1.x; As[lk+5][lr] = ra1.y; As[lk+6][lr] = ra1.z; As[lk+7][lr] = ra1.w;
        Bs[lk+0][lr] = rw0.x; Bs[lk+1][lr] = rw0.y; Bs[lk+2][lr] = rw0.z; Bs[lk+3][lr] = rw0.w;
        Bs[lk+4][lr] = rw1.x; Bs[lk+5][lr] = rw1.y; Bs[lk+6][lr] = rw1.z; Bs[lk+7][lr] = rw1.w;
        __syncthreads();
        if (kt < 240) {
            ra0 = *(const float4*)(Aptr + kt + 16);
            ra1 = *(const float4*)(Aptr + kt + 20);
            rw0 = *(const float4*)(Wptr + kt + 16);
            rw1 = *(const float4*)(Wptr + kt + 20);
        }
        #pragma unroll
        for (int k = 0; k < 16; k++) {
            float4 a0 = *(const float4*)&As[k][ty * 8];
            float4 a1 = *(const float4*)&As[k][ty * 8 + 4];
            float4 b0 = *(const float4*)&Bs[k][tx * 8];
            float4 b1 = *(const float4*)&Bs[k][tx * 8 + 4];
            u64 bp[4] = { pk2(b0.x, b0.y), pk2(b0.z, b0.w),
                          pk2(b1.x, b1.y), pk2(b1.z, b1.w) };
            float av[8] = { a0.x, a0.y, a0.z, a0.w, a1.x, a1.y, a1.z, a1.w };
            #pragma unroll
            for (int i = 0; i < 8; i++) {
                u64 ap = pk2(av[i], av[i]);
                #pragma unroll
                for (int j = 0; j < 4; j++)
                    acc[i][j] = ffma2(ap, bp[j], acc[i][j]);
            }
        }
        __syncthreads();
    }

    const int c0 = colBase + tx * 8;
    float4 bia0 = *(const float4*)&bias[c0];
    float4 bia1 = *(const float4*)&bias[c0 + 4];
    #pragma unroll
    for (int i = 0; i < 8; i++) {
        const int r = rowBase + ty * 8 + i;
        float2 v0 = up2(acc[i][0]), v1 = up2(acc[i][1]);
        float2 v2 = up2(acc[i][2]), v3 = up2(acc[i][3]);
        *(float4*)&Out[r * N + c0] =
            make_float4(v0.x + bia0.x, v0.y + bia0.y, v1.x + bia0.z, v1.y + bia0.w);
        *(float4*)&Out[r * N + c0 + 4] =
            make_float4(v2.x + bia1.x, v2.y + bia1.y, v3.x + bia1.z, v3.y + bia1.w);
    }
}

// ---------------- brute-force 1-NN, min-only tracking (round-9) -------------
// 256 blocks = 64 s-blocks x 4 candidate quarters; 4 sampling points/thread.
// Inner loop tracks only min distance per 4-candidate group (fmin tree) +
// group id; the winning slot is recovered exactly in an O(1) post-pass
// (bit-identical recompute). Tie rules preserve argmin first-min semantics.
__global__ __launch_bounds__(256)
void knn_kernel(const float* __restrict__ ipts)
{
    __shared__ __align__(16) float xs[1024];
    __shared__ __align__(16) float ys[1024];
    __shared__ __align__(16) float zs[1024];
    __shared__ __align__(16) float wsq[1024];

    const int tid  = threadIdx.x;
    const int sblk = blockIdx.x >> 2;      // 0..63
    const int q    = blockIdx.x & 3;       // candidate quarter
    const int sbase = sblk * 1024;
    const int b = sbase >> 15;
    const int cbase = b * LIN + q * 1024;

    for (int i = tid; i < 1024; i += 256) {
        float x = ipts[(cbase + i) * 3 + 0];
        float y = ipts[(cbase + i) * 3 + 1];
        float z = ipts[(cbase + i) * 3 + 2];
        xs[i] = x; ys[i] = y; zs[i] = z;
        wsq[i] = x * x + y * y + z * z;
    }
    __syncthreads();

    int   s[4], bg[4];
    float best[4];
    u64 ax2[4], ay2[4], az2[4];
    #pragma unroll
    for (int k = 0; k < 4; k++) {
        s[k] = sbase + k * 256 + tid;
        float sx = g_loc[3 * s[k] + 0];
        float sy = g_loc[3 * s[k] + 1];
        float sz = g_loc[3 * s[k] + 2];
        float ax = -2.0f * sx, ay = -2.0f * sy, az = -2.0f * sz;
        ax2[k] = pk2(ax, ax); ay2[k] = pk2(ay, ay); az2[k] = pk2(az, az);
        best[k] = 3.4e38f; bg[k] = 0;
    }

    const u64* X  = (const u64*)xs;
    const u64* Y  = (const u64*)ys;
    const u64* Z  = (const u64*)zs;
    const u64* Wq = (const u64*)wsq;

    // group g = candidates 4g..4g+3 (two u64 pairs)
    #pragma unroll 4
    for (int g = 0; g < 256; g++) {
        u64 x0 = X[2*g], x1 = X[2*g+1];
        u64 y0 = Y[2*g], y1 = Y[2*g+1];
        u64 z0 = Z[2*g], z1 = Z[2*g+1];
        u64 w0 = Wq[2*g], w1 = Wq[2*g+1];
        #pragma unroll
        for (int k = 0; k < 4; k++) {
            u64 da = ffma2(x0, ax2[k], w0);
            da = ffma2(y0, ay2[k], da);
            da = ffma2(z0, az2[k], da);
            u64 db = ffma2(x1, ax2[k], w1);
            db = ffma2(y1, ay2[k], db);
            db = ffma2(z1, az2[k], db);
            float2 fa = up2(da), fb = up2(db);
            float m = fminf(fminf(fa.x, fa.y), fminf(fb.x, fb.y));
            if (m < best[k]) { best[k] = m; bg[k] = g; }   // strict <: earliest group
        }
    }

    // post-pass: resolve exact slot inside the winning group (bit-identical)
    #pragma unroll
    for (int k = 0; k < 4; k++) {
        int g = bg[k];
        u64 da = ffma2(X[2*g],   ax2[k], Wq[2*g]);
        da = ffma2(Y[2*g],   ay2[k], da);
        da = ffma2(Z[2*g],   az2[k], da);
        u64 db = ffma2(X[2*g+1], ax2[k], Wq[2*g+1]);
        db = ffma2(Y[2*g+1], ay2[k], db);
        db = ffma2(Z[2*g+1], az2[k], db);
        float2 fa = up2(da), fb = up2(db);
        int idx = 4*g + 3;
        if (fb.x == best[k]) idx = 4*g + 2;   // reverse order: first-equal wins
        if (fa.y == best[k]) idx = 4*g + 1;
        if (fa.x == best[k]) idx = 4*g + 0;
        g_bd2[s[k]*4 + q] = best[k];
        g_bi2[s[k]*4 + q] = q * 1024 + idx;
    }
}

// ---------------- combine quarters + gather + weighted sum ------------------
__global__ __launch_bounds__(256)
void gather_kernel()
{
    const int g    = (blockIdx.x * 256 + threadIdx.x) >> 5;  // bq*8 + m
    const int lane = threadIdx.x & 31;
    const int m  = g & 7;
    const int bq = g >> 3;
    const int b  = bq >> 10;
    const int base = bq * 32 + m * 4;
    const float4 aw = *(const float4*)&g_attw[base];
    const float w4[4] = { aw.x, aw.y, aw.z, aw.w };
    float acc = 0.0f;
    #pragma unroll
    for (int p = 0; p < 4; p++) {
        const int sp4 = (base + p) * 4;
        float4 bd = *(const float4*)&g_bd2[sp4];
        int4   bi = *(const int4*)&g_bi2[sp4];
        float bdm = bd.x; int l = bi.x;            // ascending quarter, strict <
        if (bd.y < bdm) { bdm = bd.y; l = bi.y; }  // -> global first-min
        if (bd.z < bdm) { bdm = bd.z; l = bi.z; }
        if (bd.w < bdm) { bdm = bd.w; l = bi.w; }
        acc += w4[p] * g_value[(b * LIN + l) * CC + m * 32 + lane];
    }
    g_mid[bq * CC + m * 32 + lane] = acc;
}

// ---------------------------------------------------------------------------
extern "C" void kernel_launch(void* const* d_in, const int* in_sizes, int n_in,
                              void* d_out, int out_size) {
    const float* query = (const float*)d_in[0];
    const float* qpts  = (const float*)d_in[1];
    const float* inp   = (const float*)d_in[2];
    const float* ipts  = (const float*)d_in[3];
    const float* Wv    = (const float*)d_in[4];
    const float* bv    = (const float*)d_in[5];
    const float* Ws    = (const float*)d_in[6];
    const float* bs    = (const float*)d_in[7];
    const float* Wa    = (const float*)d_in[8];
    const float* ba    = (const float*)d_in[9];
    const float* Wo    = (const float*)d_in[10];
    const float* bo    = (const float*)d_in[11];
    float* out = (float*)d_out;

    float *p_value, *p_mid;
    cudaGetSymbolAddress((void**)&p_value, g_value);
    cudaGetSymbolAddress((void**)&p_mid,   g_mid);

    static cudaStream_t s1 = nullptr;
    static cudaEvent_t evFork = nullptr, evJoin = nullptr;
    if (!s1) {
        cudaStreamCreateWithFlags(&s1, cudaStreamNonBlocking);
        cudaEventCreateWithFlags(&evFork, cudaEventDisableTiming);
        cudaEventCreateWithFlags(&evJoin, cudaEventDisableTiming);
    }

    // fork: value GEMM on side stream (independent of proj/knn)
    cudaEventRecord(evFork, 0);
    cudaStreamWaitEvent(s1, evFork, 0);
    sgemm128<<<dim3(2, 64), 256, 0, s1>>>(inp, Wv, bv, p_value, 256);
    cudaEventRecord(evJoin, s1);

    // main stream: proj (-> g_loc, g_attw), then KNN
    sgemm_nt<1><<<dim3(2, 32), 256>>>(query, Ws, Wa, 96, bs, ba,
                                      nullptr, 128, qpts);
    knn_kernel<<<256, 256>>>(ipts);

    // join: gather needs both knn results and g_value
    cudaStreamWaitEvent(0, evJoin, 0);
    gather_kernel<<<2048, 256>>>();
    // output projection: 32x64 tiles, 256 blocks (2/SM) for latency hiding
    sgemm32x64<<<dim3(4, 64), 256>>>(p_mid, Wo, bo, out, 256);
}